// round 16
// baseline (speedup 1.0000x reference)
#include <cuda_runtime.h>
#include <cuda_fp16.h>
#include <math.h>
#include <stdint.h>

#define DIM   1024
#define NUM_F 16
#define NB    4
#define SEQ   2048
#define MTOK  (NB * SEQ)   // 8192

// ======================= scratch (static device globals) ====================
__device__ __half  g_ph[MTOK * SEQ];      // unnormalized exp(scores), fp16
__device__ float   g_inv[MTOK];           // per-row 1/sum
__device__ __half  g_vt[MTOK * DIM];      // v^T [NB][DIM][SEQ] fp16
__device__ float g_kanq[MTOK * NUM_F];
__device__ float g_kank[MTOK * NUM_F];
__device__ __half g_Cf[32 * DIM];         // folded C (rows 0-15 q, 16-31 k) fp16
__device__ float g_cq[NUM_F];
__device__ float g_ck[NUM_F];
__device__ unsigned g_maxk_bits[NB];      // max |k|^2 per batch (fp32 bits)

// ======================= helpers ============================================
__device__ __forceinline__ uint32_t smem_u32(const void* p) {
    uint32_t a;
    asm("{ .reg .u64 t; cvta.to.shared.u64 t, %1; cvt.u32.u64 %0, t; }"
        : "=r"(a) : "l"(p));
    return a;
}
__device__ __forceinline__ void ldmx4(uint32_t* r, uint32_t addr) {
    asm volatile("ldmatrix.sync.aligned.m8n8.x4.shared.b16 {%0,%1,%2,%3}, [%4];"
        : "=r"(r[0]), "=r"(r[1]), "=r"(r[2]), "=r"(r[3]) : "r"(addr));
}
__device__ __forceinline__ void ldmx2(uint32_t* r, uint32_t addr) {
    asm volatile("ldmatrix.sync.aligned.m8n8.x2.shared.b16 {%0,%1}, [%2];"
        : "=r"(r[0]), "=r"(r[1]) : "r"(addr));
}
__device__ __forceinline__ void mma_f16(float* c, const uint32_t* a, const uint32_t* b) {
    asm volatile("mma.sync.aligned.m16n8k16.row.col.f32.f16.f16.f32 "
        "{%0,%1,%2,%3}, {%4,%5,%6,%7}, {%8,%9}, {%0,%1,%2,%3};"
        : "+f"(c[0]), "+f"(c[1]), "+f"(c[2]), "+f"(c[3])
        : "r"(a[0]), "r"(a[1]), "r"(a[2]), "r"(a[3]), "r"(b[0]), "r"(b[1]));
}
__device__ __forceinline__ uint32_t pack2hf(float a, float b) {
    __half2 t = __floats2half2_rn(a, b);
    return *(uint32_t*)&t;
}
// Load 8 consecutive fp32, round to fp16, pack to uint4 (16 B).
__device__ __forceinline__ uint4 ld8_f32_to_h8(const float* p) {
    float4 a = *(const float4*)p;
    float4 b = *(const float4*)(p + 4);
    return make_uint4(pack2hf(a.x, a.y), pack2hf(a.z, a.w),
                      pack2hf(b.x, b.y), pack2hf(b.z, b.w));
}
// exp via FMA pipe (no MUFU): exp(x) = 2^(x*log2e), degree-6 poly on frac.
__device__ __forceinline__ float fexp(float x) {
    float t = fmaxf(x * 1.4426950408889634f, -120.f);
    float fl = floorf(t);
    float f = t - fl;
    float p = 1.5403530e-4f;
    p = fmaf(p, f, 1.3333558e-3f);
    p = fmaf(p, f, 9.6181291e-3f);
    p = fmaf(p, f, 5.5504109e-2f);
    p = fmaf(p, f, 2.4022651e-1f);
    p = fmaf(p, f, 6.9314718e-1f);
    p = fmaf(p, f, 1.0f);
    int i = (int)fl;
    return p * __int_as_float((uint32_t)(i + 127) << 23);
}

// ======================= K1: fold basis into Wq/Wk (fp16 out) ===============
__global__ void fold_kernel(const float* __restrict__ basis,
                            const float* __restrict__ Wq, const float* __restrict__ bq,
                            const float* __restrict__ Wk, const float* __restrict__ bk)
{
    if (blockIdx.x == 0 && blockIdx.y == 0 && threadIdx.x < NB)
        g_maxk_bits[threadIdx.x] = 0u;           // reset per call (deterministic)
    int d = blockIdx.x * blockDim.x + threadIdx.x;
    int f = blockIdx.y;
    const float* W  = (f < 16) ? Wq : Wk;
    const float* br = basis + (size_t)(f & 15) * DIM;
    float a = 0.f;
    for (int e = 0; e < DIM; e++)
        a = fmaf(br[e], W[(size_t)e * DIM + d], a);
    g_Cf[f * DIM + d] = __float2half(a);
    if (blockIdx.x == 0 && threadIdx.x == 0) {
        const float* bb = (f < 16) ? bq : bk;
        float s = 0.f;
        for (int e = 0; e < DIM; e++) s = fmaf(br[e], bb[e], s);
        if (f < 16) g_cq[f] = s; else g_ck[f - 16] = s;
    }
}

// ======================= K2: kan via mma.sync  [8192,32] = x @ C^T ==========
// x read fp32, converted to fp16 inline (bit-identical to pre-pass).
#define KSTR 40
__global__ __launch_bounds__(128) void kan_mma_kernel(const float* __restrict__ x)
{
    __shared__ __align__(16) __half sX[2][64 * KSTR];
    __shared__ __align__(16) __half sC[2][32 * KSTR];
    const int tid = threadIdx.x;
    const int lane = tid & 31, wid = tid >> 5;
    const int m0 = blockIdx.x * 64;

    const int xc1 = tid + 128;
    const int xr0 = tid >> 2, xk0 = (tid & 3) * 8;
    const int xr1 = xc1 >> 2, xk1 = (xc1 & 3) * 8;
    const uint32_t xs0 = (uint32_t)(xr0 * KSTR + xk0) * 2;
    const uint32_t xs1 = (uint32_t)(xr1 * KSTR + xk1) * 2;
    const int cr = tid >> 2, ck = (tid & 3) * 8;
    const uint32_t cs = (uint32_t)(cr * KSTR + ck) * 2;

    float acc[4][4];
#pragma unroll
    for (int ni = 0; ni < 4; ni++)
#pragma unroll
        for (int rr = 0; rr < 4; rr++) acc[ni][rr] = 0.f;

    const int arow = wid * 16 + (lane & 15);
    const int acol = (lane >> 4) * 8;
    const int brow = lane & 7;
    const int bcol = ((lane >> 3) & 1) * 8;

    uint4 r0v, r1v, r2v;
#define KLOAD(K0) do {                                                            \
        r0v = ld8_f32_to_h8(x + (size_t)(m0 + xr0) * DIM + (K0) + xk0);           \
        r1v = ld8_f32_to_h8(x + (size_t)(m0 + xr1) * DIM + (K0) + xk1);           \
        r2v = *(const uint4*)(g_Cf + (size_t)cr * DIM + (K0) + ck);               \
    } while (0)
#define KSTORE(S) do {                                                            \
        *(uint4*)((char*)sX[S] + xs0) = r0v;                                      \
        *(uint4*)((char*)sX[S] + xs1) = r1v;                                      \
        *(uint4*)((char*)sC[S] + cs)  = r2v;                                      \
    } while (0)

    KLOAD(0);
    KSTORE(0);
    __syncthreads();

    const int T = DIM / 32;
    for (int t = 0; t < T; t++) {
        if (t + 1 < T) KLOAD((t + 1) * 32);
        const uint32_t uX = smem_u32(sX[t & 1]);
        const uint32_t uC = smem_u32(sC[t & 1]);
#pragma unroll
        for (int kk = 0; kk < 32; kk += 16) {
            uint32_t ah[4], bh[4][2];
            uint32_t ad = (uint32_t)((arow * KSTR + kk + acol) * 2);
            ldmx4(ah, uX + ad);
#pragma unroll
            for (int ni = 0; ni < 4; ni++) {
                uint32_t bd = (uint32_t)(((brow + ni * 8) * KSTR + kk + bcol) * 2);
                ldmx2(bh[ni], uC + bd);
            }
#pragma unroll
            for (int ni = 0; ni < 4; ni++)
                mma_f16(acc[ni], ah, bh[ni]);
        }
        if (t + 1 < T) {
            __syncthreads();
            KSTORE((t + 1) & 1);
            __syncthreads();
        }
    }
#undef KLOAD
#undef KSTORE

    int r0 = m0 + wid * 16 + (lane >> 2);
#pragma unroll
    for (int ni = 0; ni < 4; ni++) {
        int col = ni * 8 + (lane & 3) * 2;
#pragma unroll
        for (int cdx = 0; cdx < 2; cdx++) {
            int c = col + cdx;
            float bias = (c < 16) ? g_cq[c] : g_ck[c - 16];
            float* dst = (c < 16) ? g_kanq : g_kank;
            int f = c & 15;
            dst[(size_t)r0 * NUM_F + f]       = acc[ni][cdx]     + bias;
            dst[(size_t)(r0 + 8) * NUM_F + f] = acc[ni][cdx + 2] + bias;
        }
    }
}

// ======================= K2b: per-batch max |k|^2 ===========================
__global__ void knorm_kernel()
{
    int r = blockIdx.x * 256 + threadIdx.x;   // 0..8191
    const float4* kr = (const float4*)(g_kank + (size_t)r * NUM_F);
    float s = 0.f;
#pragma unroll
    for (int i = 0; i < 4; i++) {
        float4 v = kr[i];
        s += v.x * v.x + v.y * v.y + v.z * v.z + v.w * v.w;
    }
#pragma unroll
    for (int off = 16; off; off >>= 1)
        s = fmaxf(s, __shfl_xor_sync(0xffffffffu, s, off));
    if ((threadIdx.x & 31) == 0)
        atomicMax(&g_maxk_bits[r >> 11], __float_as_uint(s));
}

// ======================= K4: fused scores + softmax (single pass) ===========
#define ACH 256
__global__ __launch_bounds__(256) void attn_kernel()
{
    __shared__ __align__(16) float sK[ACH][20];
    const int tid = threadIdx.x;
    const int lane = tid & 31, wid = tid >> 5;
    const int blk = blockIdx.x;          // 128 blocks, 64 rows each
    const int b = blk >> 5;
    const int r0 = (blk & 31) * 64;
    const float maxk = sqrtf(__uint_as_float(g_maxk_bits[b]));
    const float inv32 = 1.0f / 32.0f;

    for (int p = 0; p < 2; p++) {
        const int rbase = r0 + wid * 8 + p * 4;
        float q[4][16], bound[4], sum[4];
#pragma unroll
        for (int i = 0; i < 4; i++) {
            const float* qr = g_kanq + (size_t)(b * SEQ + rbase + i) * NUM_F;
            float qs = 0.f;
#pragma unroll
            for (int f = 0; f < 16; f++) { q[i][f] = qr[f]; qs = fmaf(qr[f], qr[f], qs); }
            bound[i] = sqrtf(qs) * maxk;
            sum[i] = 0.f;
        }

        for (int c = 0; c < SEQ / ACH; c++) {
            __syncthreads();
#pragma unroll
            for (int u = 0; u < 4; u++) {
                int e4 = tid + u * 256;
                int kr = e4 >> 2, kf = (e4 & 3) * 4;
                *(float4*)&sK[kr][kf] =
                    *(const float4*)(g_kank + (size_t)(b * SEQ + c * ACH + kr) * NUM_F + kf);
            }
            __syncthreads();
#pragma unroll
            for (int kg = 0; kg < ACH / 64; kg++) {
                int jj = kg * 64 + lane * 2;
                float k0[16], k1[16];
                *(float4*)&k0[0]  = *(const float4*)&sK[jj][0];
                *(float4*)&k0[4]  = *(const float4*)&sK[jj][4];
                *(float4*)&k0[8]  = *(const float4*)&sK[jj][8];
                *(float4*)&k0[12] = *(const float4*)&sK[jj][12];
                *(float4*)&k1[0]  = *(const float4*)&sK[jj + 1][0];
                *(float4*)&k1[4]  = *(const float4*)&sK[jj + 1][4];
                *(float4*)&k1[8]  = *(const float4*)&sK[jj + 1][8];
                *(float4*)&k1[12] = *(const float4*)&sK[jj + 1][12];
                size_t jbase = (size_t)(b * SEQ) * SEQ + (size_t)c * ACH + jj;
#pragma unroll
                for (int i = 0; i < 4; i++) {
                    float s0 = 0.f, s1 = 0.f;
#pragma unroll
                    for (int f = 0; f < 16; f++) {
                        s0 = fmaf(q[i][f], k0[f], s0);
                        s1 = fmaf(q[i][f], k1[f], s1);
                    }
                    float e0 = fexp((s0 - bound[i]) * inv32);
                    float e1 = fexp((s1 - bound[i]) * inv32);
                    sum[i] += e0 + e1;
                    ((uint32_t*)g_ph)[(jbase + (size_t)(rbase + i) * SEQ) >> 1] =
                        pack2hf(e0, e1);
                }
            }
        }
#pragma unroll
        for (int i = 0; i < 4; i++) {
#pragma unroll
            for (int off = 16; off; off >>= 1)
                sum[i] += __shfl_xor_sync(0xffffffffu, sum[i], off);
            if (lane == 0) g_inv[b * SEQ + rbase + i] = 1.0f / sum[i];
        }
        __syncthreads();
    }
}

// ======================= persistent single-fp16 GEMMs =======================
// Block 128x128 tile, 8 warps each 64x32, BK=32, double-buffered LDG->reg->STS.
#define MSTRIDE 40
#define TILE_B  (128 * MSTRIDE * 2)     // 10240 B
#define GM_SMEM (4 * TILE_B)            // 40960 B

// K3: v = x @ Wv^T + bv -> vT fp16.  Inline fp32->fp16 conversion of x and Wv.
__global__ __launch_bounds__(256, 2) void mma_gemm_xw(
    const float* __restrict__ x, const float* __restrict__ Wv,
    const float* __restrict__ bias)
{
    extern __shared__ char smem[];
    const uint32_t sb = smem_u32(smem);
    const int tid  = threadIdx.x;
    const int lane = tid & 31, wid = tid >> 5;
    const int warp_m = wid & 1, warp_n = wid >> 1;

    const int c1 = tid + 256;
    const int ar0 = tid >> 2, ak0 = (tid & 3) * 8;
    const int ar1 = c1 >> 2,  ak1 = (c1 & 3) * 8;
    const uint32_t s0 = (uint32_t)(ar0 * MSTRIDE + ak0) * 2;
    const uint32_t s1 = (uint32_t)(ar1 * MSTRIDE + ak1) * 2;
    const int arow = warp_m * 64 + (lane & 15);
    const int acol = (lane >> 4) * 8;
    const int brow = warp_n * 32 + (lane & 7);
    const int bcol = ((lane >> 3) & 1) * 8;
    const int T = DIM >> 5;

    for (int tile = blockIdx.x; tile < 512; tile += gridDim.x) {
        const int m0 = (tile >> 3) * 128, n0 = (tile & 7) * 128;
        const size_t gA0 = (size_t)(m0 + ar0) * DIM + ak0;
        const size_t gA1 = (size_t)(m0 + ar1) * DIM + ak1;
        const size_t gB0 = (size_t)(n0 + ar0) * DIM + ak0;
        const size_t gB1 = (size_t)(n0 + ar1) * DIM + ak1;

        float acc[4][4][4];
#pragma unroll
        for (int mi = 0; mi < 4; mi++)
#pragma unroll
            for (int ni = 0; ni < 4; ni++)
#pragma unroll
                for (int rr = 0; rr < 4; rr++) acc[mi][ni][rr] = 0.f;

        uint4 rg[4];
#define LOADG(K0) do {                                                 \
            rg[0] = ld8_f32_to_h8(x  + gA0 + (K0));                    \
            rg[1] = ld8_f32_to_h8(x  + gA1 + (K0));                    \
            rg[2] = ld8_f32_to_h8(Wv + gB0 + (K0));                    \
            rg[3] = ld8_f32_to_h8(Wv + gB1 + (K0));                    \
        } while (0)
#define STORES(S) do {                                                 \
            char* base = smem + (S) * 2 * TILE_B;                      \
            *(uint4*)(base + s0)          = rg[0];                     \
            *(uint4*)(base + s1)          = rg[1];                     \
            *(uint4*)(base + TILE_B + s0) = rg[2];                     \
            *(uint4*)(base + TILE_B + s1) = rg[3];                     \
        } while (0)

        LOADG(0);
        __syncthreads();          // smem free of previous tile's readers
        STORES(0);
        __syncthreads();

        for (int t = 0; t < T; t++) {
            if (t + 1 < T) LOADG((t + 1) << 5);
            uint32_t base = sb + (uint32_t)(t & 1) * 2 * TILE_B;
#pragma unroll
            for (int kk = 0; kk < 32; kk += 16) {
                uint32_t ah[4][4], bh[4][2];
#pragma unroll
                for (int mi = 0; mi < 4; mi++) {
                    uint32_t ad = (uint32_t)(((arow + mi * 16) * MSTRIDE + kk + acol) * 2);
                    ldmx4(ah[mi], base + ad);
                }
#pragma unroll
                for (int ni = 0; ni < 4; ni++) {
                    uint32_t bd = (uint32_t)(((brow + ni * 8) * MSTRIDE + kk + bcol) * 2);
                    ldmx2(bh[ni], base + TILE_B + bd);
                }
#pragma unroll
                for (int mi = 0; mi < 4; mi++)
#pragma unroll
                    for (int ni = 0; ni < 4; ni++)
                        mma_f16(acc[mi][ni], ah[mi], bh[ni]);
            }
            if (t + 1 < T) {
                STORES((t + 1) & 1);
                __syncthreads();
            }
        }
#undef LOADG
#undef STORES

        // epilogue: two 64-column halves, buffer [64][132] f32 in smem
        float* st = (float*)smem;
        int bz  = m0 >> 11;
        int m0s = m0 & (SEQ - 1);
#pragma unroll
        for (int half = 0; half < 2; half++) {
            __syncthreads();
            if ((warp_n >> 1) == half) {
                int wn = warp_n & 1;
#pragma unroll
                for (int mi = 0; mi < 4; mi++) {
                    int rowl = warp_m * 64 + mi * 16 + (lane >> 2);
#pragma unroll
                    for (int ni = 0; ni < 4; ni++) {
                        int coll = wn * 32 + ni * 8 + (lane & 3) * 2;
                        int gcol = half * 64 + coll;
                        float b0 = bias[n0 + gcol], b1 = bias[n0 + gcol + 1];
                        st[coll * 132 + rowl]           = acc[mi][ni][0] + b0;
                        st[(coll + 1) * 132 + rowl]     = acc[mi][ni][1] + b1;
                        st[coll * 132 + rowl + 8]       = acc[mi][ni][2] + b0;
                        st[(coll + 1) * 132 + rowl + 8] = acc[mi][ni][3] + b1;
                    }
                }
            }
            __syncthreads();
            for (int w = tid; w < 64 * 64; w += 256) {
                int d = w >> 6, mp = w & 63;
                float v0 = st[d * 132 + mp * 2];
                float v1 = st[d * 132 + mp * 2 + 1];
                size_t idx = (((size_t)(bz * DIM + n0 + half * 64 + d) * SEQ + m0s) >> 1) + mp;
                ((uint32_t*)g_vt)[idx] = pack2hf(v0, v1);
            }
        }
    }
}

// K5: out = (P @ v) * inv_sum.  512 tiles = 4 z x 16 m x 8 n.
__global__ __launch_bounds__(256, 2) void mma_gemm_pv(float* __restrict__ Cout)
{
    extern __shared__ char smem[];
    const uint32_t sb = smem_u32(smem);
    const int tid  = threadIdx.x;
    const int lane = tid & 31, wid = tid >> 5;
    const int warp_m = wid & 1, warp_n = wid >> 1;

    const int c1 = tid + 256;
    const int ar0 = tid >> 2, ak0 = (tid & 3) * 8;
    const int ar1 = c1 >> 2,  ak1 = (c1 & 3) * 8;
    const uint32_t s0 = (uint32_t)(ar0 * MSTRIDE + ak0) * 2;
    const uint32_t s1 = (uint32_t)(ar1 * MSTRIDE + ak1) * 2;
    const int arow = warp_m * 64 + (lane & 15);
    const int acol = (lane >> 4) * 8;
    const int brow = warp_n * 32 + (lane & 7);
    const int bcol = ((lane >> 3) & 1) * 8;
    const int T = SEQ >> 5;

    for (int tile = blockIdx.x; tile < 512; tile += gridDim.x) {
        const int z  = tile & 3;
        const int tt = tile >> 2;
        const int m0 = (tt >> 3) * 128, n0 = (tt & 7) * 128;
        const __half* pP = g_ph + (size_t)z * SEQ * SEQ;
        const __half* pV = g_vt + (size_t)z * DIM * SEQ;
        const size_t gA0 = (size_t)(m0 + ar0) * SEQ + ak0;
        const size_t gA1 = (size_t)(m0 + ar1) * SEQ + ak1;
        const size_t gB0 = (size_t)(n0 + ar0) * SEQ + ak0;
        const size_t gB1 = (size_t)(n0 + ar1) * SEQ + ak1;

        float acc[4][4][4];
#pragma unroll
        for (int mi = 0; mi < 4; mi++)
#pragma unroll
            for (int ni = 0; ni < 4; ni++)
#pragma unroll
                for (int rr = 0; rr < 4; rr++) acc[mi][ni][rr] = 0.f;

        uint4 rg[4];
#define PLOADG(K0) do {                                                \
            rg[0] = *(const uint4*)(pP + gA0 + (K0));                  \
            rg[1] = *(const uint4*)(pP + gA1 + (K0));                  \
            rg[2] = *(const uint4*)(pV + gB0 + (K0));                  \
            rg[3] = *(const uint4*)(pV + gB1 + (K0));                  \
        } while (0)
#define PSTORES(S) do {                                                \
            char* base = smem + (S) * 2 * TILE_B;                      \
            *(uint4*)(base + s0)          = rg[0];                     \
            *(uint4*)(base + s1)          = rg[1];                     \
            *(uint4*)(base + TILE_B + s0) = rg[2];                     \
            *(uint4*)(base + TILE_B + s1) = rg[3];                     \
        } while (0)

        PLOADG(0);
        __syncthreads();          // smem free of previous tile's readers
        PSTORES(0);
        __syncthreads();

        for (int t = 0; t < T; t++) {
            if (t + 1 < T) PLOADG((t + 1) << 5);
            uint32_t base = sb + (uint32_t)(t & 1) * 2 * TILE_B;
#pragma unroll
            for (int kk = 0; kk < 32; kk += 16) {
                uint32_t ah[4][4], bh[4][2];
#pragma unroll
                for (int mi = 0; mi < 4; mi++) {
                    uint32_t ad = (uint32_t)(((arow + mi * 16) * MSTRIDE + kk + acol) * 2);
                    ldmx4(ah[mi], base + ad);
                }
#pragma unroll
                for (int ni = 0; ni < 4; ni++) {
                    uint32_t bd = (uint32_t)(((brow + ni * 8) * MSTRIDE + kk + bcol) * 2);
                    ldmx2(bh[ni], base + TILE_B + bd);
                }
#pragma unroll
                for (int mi = 0; mi < 4; mi++)
#pragma unroll
                    for (int ni = 0; ni < 4; ni++)
                        mma_f16(acc[mi][ni], ah[mi], bh[ni]);
            }
            if (t + 1 < T) {
                PSTORES((t + 1) & 1);
                __syncthreads();
            }
        }
#undef PLOADG
#undef PSTORES

        float* C = Cout + (size_t)z * SEQ * DIM;
#pragma unroll
        for (int mi = 0; mi < 4; mi++) {
            int rowl = warp_m * 64 + mi * 16 + (lane >> 2);
            float inv0 = g_inv[z * SEQ + m0 + rowl];
            float inv1 = g_inv[z * SEQ + m0 + rowl + 8];
#pragma unroll
            for (int ni = 0; ni < 4; ni++) {
                int col = n0 + warp_n * 32 + ni * 8 + (lane & 3) * 2;
                *(float2*)&C[(size_t)(m0 + rowl) * DIM + col] =
                    make_float2(acc[mi][ni][0] * inv0, acc[mi][ni][1] * inv0);
                *(float2*)&C[(size_t)(m0 + rowl + 8) * DIM + col] =
                    make_float2(acc[mi][ni][2] * inv1, acc[mi][ni][3] * inv1);
            }
        }
    }
}

// ======================= launch =============================================
extern "C" void kernel_launch(void* const* d_in, const int* in_sizes, int n_in,
                              void* d_out, int out_size)
{
    const float* x     = (const float*)d_in[0];
    const float* basis = (const float*)d_in[1];
    const float* Wq    = (const float*)d_in[2];
    const float* bq    = (const float*)d_in[3];
    const float* Wk    = (const float*)d_in[4];
    const float* bk    = (const float*)d_in[5];
    const float* Wv    = (const float*)d_in[6];
    const float* bv    = (const float*)d_in[7];
    float* out = (float*)d_out;

    int sms = 148;
    cudaDeviceGetAttribute(&sms, cudaDevAttrMultiProcessorCount, 0);
    int gemm_grid = 2 * sms;

    cudaFuncSetAttribute(mma_gemm_xw, cudaFuncAttributeMaxDynamicSharedMemorySize, GM_SMEM);
    cudaFuncSetAttribute(mma_gemm_pv, cudaFuncAttributeMaxDynamicSharedMemorySize, GM_SMEM);

    // fold (fp16 C + biases + maxk reset)
    fold_kernel<<<dim3(4, 32), 256>>>(basis, Wq, bq, Wk, bk);

    // kan via mma.sync (inline fp32->fp16 x) + per-batch key max
    kan_mma_kernel<<<MTOK / 64, 128>>>(x);
    knorm_kernel<<<MTOK / 256, 256>>>();

    // K3: v = x @ Wv^T + bv -> vT fp16 (persistent, inline conversion)
    mma_gemm_xw<<<gemm_grid, 256, GM_SMEM>>>(x, Wv, bv);

    // K4: fused scores + softmax (unnormalized exp fp16 + 1/sum)
    attn_kernel<<<MTOK / 64, 256>>>();

    // K5: out = (P @ v) * inv_sum  (persistent)
    mma_gemm_pv<<<gemm_grid, 256, GM_SMEM>>>(out);
}

// round 17
// speedup vs baseline: 1.0900x; 1.0900x over previous
#include <cuda_runtime.h>
#include <cuda_fp16.h>
#include <math.h>
#include <stdint.h>

#define DIM   1024
#define NUM_F 16
#define NB    4
#define SEQ   2048
#define MTOK  (NB * SEQ)   // 8192

// ======================= scratch (static device globals) ====================
__device__ __half  g_ph[MTOK * SEQ];      // unnormalized exp(scores), fp16
__device__ float   g_inv[MTOK];           // per-row 1/sum
__device__ __half  g_xf[MTOK * DIM];      // x fp16
__device__ __half  g_wf[DIM * DIM];       // Wv fp16
__device__ __half  g_vt[MTOK * DIM];      // v^T [NB][DIM][SEQ] fp16
__device__ float g_kanq[MTOK * NUM_F];
__device__ float g_kank[MTOK * NUM_F];
__device__ __half g_Cf[32 * DIM];         // folded C (rows 0-15 q, 16-31 k) fp16
__device__ float g_cq[NUM_F];
__device__ float g_ck[NUM_F];
__device__ unsigned g_maxk_bits[NB];      // max |k|^2 per batch (fp32 bits)

// ======================= helpers ============================================
__device__ __forceinline__ uint32_t smem_u32(const void* p) {
    uint32_t a;
    asm("{ .reg .u64 t; cvta.to.shared.u64 t, %1; cvt.u32.u64 %0, t; }"
        : "=r"(a) : "l"(p));
    return a;
}
__device__ __forceinline__ void ldmx4(uint32_t* r, uint32_t addr) {
    asm volatile("ldmatrix.sync.aligned.m8n8.x4.shared.b16 {%0,%1,%2,%3}, [%4];"
        : "=r"(r[0]), "=r"(r[1]), "=r"(r[2]), "=r"(r[3]) : "r"(addr));
}
__device__ __forceinline__ void mma_f16(float* c, const uint32_t* a, const uint32_t* b) {
    asm volatile("mma.sync.aligned.m16n8k16.row.col.f32.f16.f16.f32 "
        "{%0,%1,%2,%3}, {%4,%5,%6,%7}, {%8,%9}, {%0,%1,%2,%3};"
        : "+f"(c[0]), "+f"(c[1]), "+f"(c[2]), "+f"(c[3])
        : "r"(a[0]), "r"(a[1]), "r"(a[2]), "r"(a[3]), "r"(b[0]), "r"(b[1]));
}
__device__ __forceinline__ uint32_t pack2hf(float a, float b) {
    __half2 t = __floats2half2_rn(a, b);
    return *(uint32_t*)&t;
}
// exp via FMA pipe (no MUFU): exp(x) = 2^(x*log2e), degree-6 poly on frac.
__device__ __forceinline__ float fexp(float x) {
    float t = fmaxf(x * 1.4426950408889634f, -120.f);
    float fl = floorf(t);
    float f = t - fl;
    float p = 1.5403530e-4f;
    p = fmaf(p, f, 1.3333558e-3f);
    p = fmaf(p, f, 9.6181291e-3f);
    p = fmaf(p, f, 5.5504109e-2f);
    p = fmaf(p, f, 2.4022651e-1f);
    p = fmaf(p, f, 6.9314718e-1f);
    p = fmaf(p, f, 1.0f);
    int i = (int)fl;
    return p * __int_as_float((uint32_t)(i + 127) << 23);
}

// ======================= K1: fold basis into Wq/Wk (fp16 out) ===============
__global__ void fold_kernel(const float* __restrict__ basis,
                            const float* __restrict__ Wq, const float* __restrict__ bq,
                            const float* __restrict__ Wk, const float* __restrict__ bk)
{
    if (blockIdx.x == 0 && blockIdx.y == 0 && threadIdx.x < NB)
        g_maxk_bits[threadIdx.x] = 0u;           // reset per call (deterministic)
    int d = blockIdx.x * blockDim.x + threadIdx.x;
    int f = blockIdx.y;
    const float* W  = (f < 16) ? Wq : Wk;
    const float* br = basis + (size_t)(f & 15) * DIM;
    float a = 0.f;
    for (int e = 0; e < DIM; e++)
        a = fmaf(br[e], W[(size_t)e * DIM + d], a);
    g_Cf[f * DIM + d] = __float2half(a);
    if (blockIdx.x == 0 && threadIdx.x == 0) {
        const float* bb = (f < 16) ? bq : bk;
        float s = 0.f;
        for (int e = 0; e < DIM; e++) s = fmaf(br[e], bb[e], s);
        if (f < 16) g_cq[f] = s; else g_ck[f - 16] = s;
    }
}

// ======================= fp32 -> fp16 conversion (x and Wv in one launch) ===
#define NX4 (MTOK * DIM / 4)
#define NW4 (DIM * DIM / 4)
__global__ void tohalf2_kernel(const float* __restrict__ x, const float* __restrict__ w)
{
    int i = blockIdx.x * blockDim.x + threadIdx.x;
    const float* src;
    __half* dst;
    int j;
    if (i < NX4) { src = x; dst = g_xf; j = i; }
    else         { src = w; dst = g_wf; j = i - NX4; }
    float4 v = ((const float4*)src)[j];
    ((uint2*)dst)[j] = make_uint2(pack2hf(v.x, v.y), pack2hf(v.z, v.w));
}

// ======================= K2: kan via mma.sync  [8192,32] = x @ C^T (fp16) ===
#define KSTR 40
__global__ __launch_bounds__(128) void kan_mma_kernel()
{
    __shared__ __align__(16) __half sX[2][64 * KSTR];
    __shared__ __align__(16) __half sC[2][32 * KSTR];
    const int tid = threadIdx.x;
    const int lane = tid & 31, wid = tid >> 5;
    const int m0 = blockIdx.x * 64;

    const int xc1 = tid + 128;
    const int xr0 = tid >> 2, xk0 = (tid & 3) * 8;
    const int xr1 = xc1 >> 2, xk1 = (xc1 & 3) * 8;
    const uint32_t xs0 = (uint32_t)(xr0 * KSTR + xk0) * 2;
    const uint32_t xs1 = (uint32_t)(xr1 * KSTR + xk1) * 2;
    const int cr = tid >> 2, ck = (tid & 3) * 8;
    const uint32_t cs = (uint32_t)(cr * KSTR + ck) * 2;

    float acc[4][4];
#pragma unroll
    for (int ni = 0; ni < 4; ni++)
#pragma unroll
        for (int rr = 0; rr < 4; rr++) acc[ni][rr] = 0.f;

    const int arow = wid * 16 + (lane & 15);
    const int acol = (lane >> 4) * 8;
    // B x4 addressing: lanes 0-15 -> first n8 tile of pair, 16-31 -> second
    const int brow4 = (lane & 7) + ((lane >> 4) & 1) * 8;
    const int bcol4 = ((lane >> 3) & 1) * 8;

    uint4 r0v, r1v, r2v;
#define KLOAD(K0) do {                                                            \
        r0v = *(const uint4*)(g_xf + (size_t)(m0 + xr0) * DIM + (K0) + xk0);      \
        r1v = *(const uint4*)(g_xf + (size_t)(m0 + xr1) * DIM + (K0) + xk1);      \
        r2v = *(const uint4*)(g_Cf + (size_t)cr * DIM + (K0) + ck);               \
    } while (0)
#define KSTORE(S) do {                                                            \
        *(uint4*)((char*)sX[S] + xs0) = r0v;                                      \
        *(uint4*)((char*)sX[S] + xs1) = r1v;                                      \
        *(uint4*)((char*)sC[S] + cs)  = r2v;                                      \
    } while (0)

    KLOAD(0);
    KSTORE(0);
    __syncthreads();

    const int T = DIM / 32;
    for (int t = 0; t < T; t++) {
        if (t + 1 < T) KLOAD((t + 1) * 32);
        const uint32_t uX = smem_u32(sX[t & 1]);
        const uint32_t uC = smem_u32(sC[t & 1]);
#pragma unroll
        for (int kk = 0; kk < 32; kk += 16) {
            uint32_t ah[4], bh[4][2];
            uint32_t ad = (uint32_t)((arow * KSTR + kk + acol) * 2);
            ldmx4(ah, uX + ad);
#pragma unroll
            for (int p = 0; p < 2; p++) {
                uint32_t bd = (uint32_t)(((brow4 + p * 16) * KSTR + kk + bcol4) * 2);
                ldmx4(&bh[p * 2][0], uC + bd);
            }
#pragma unroll
            for (int ni = 0; ni < 4; ni++)
                mma_f16(acc[ni], ah, bh[ni]);
        }
        if (t + 1 < T) {
            __syncthreads();
            KSTORE((t + 1) & 1);
            __syncthreads();
        }
    }
#undef KLOAD
#undef KSTORE

    int r0 = m0 + wid * 16 + (lane >> 2);
#pragma unroll
    for (int ni = 0; ni < 4; ni++) {
        int col = ni * 8 + (lane & 3) * 2;
#pragma unroll
        for (int cdx = 0; cdx < 2; cdx++) {
            int c = col + cdx;
            float bias = (c < 16) ? g_cq[c] : g_ck[c - 16];
            float* dst = (c < 16) ? g_kanq : g_kank;
            int f = c & 15;
            dst[(size_t)r0 * NUM_F + f]       = acc[ni][cdx]     + bias;
            dst[(size_t)(r0 + 8) * NUM_F + f] = acc[ni][cdx + 2] + bias;
        }
    }
}

// ======================= K2b: per-batch max |k|^2 ===========================
__global__ void knorm_kernel()
{
    int r = blockIdx.x * 256 + threadIdx.x;   // 0..8191
    const float4* kr = (const float4*)(g_kank + (size_t)r * NUM_F);
    float s = 0.f;
#pragma unroll
    for (int i = 0; i < 4; i++) {
        float4 v = kr[i];
        s += v.x * v.x + v.y * v.y + v.z * v.z + v.w * v.w;
    }
#pragma unroll
    for (int off = 16; off; off >>= 1)
        s = fmaxf(s, __shfl_xor_sync(0xffffffffu, s, off));
    if ((threadIdx.x & 31) == 0)
        atomicMax(&g_maxk_bits[r >> 11], __float_as_uint(s));
}

// ======================= K4: fused scores + softmax (single pass) ===========
#define ACH 256
__global__ __launch_bounds__(256) void attn_kernel()
{
    __shared__ __align__(16) float sK[ACH][20];
    const int tid = threadIdx.x;
    const int lane = tid & 31, wid = tid >> 5;
    const int blk = blockIdx.x;          // 128 blocks, 64 rows each
    const int b = blk >> 5;
    const int r0 = (blk & 31) * 64;
    const float maxk = sqrtf(__uint_as_float(g_maxk_bits[b]));
    const float inv32 = 1.0f / 32.0f;

    for (int p = 0; p < 2; p++) {
        const int rbase = r0 + wid * 8 + p * 4;
        float q[4][16], bound[4], sum[4];
#pragma unroll
        for (int i = 0; i < 4; i++) {
            const float* qr = g_kanq + (size_t)(b * SEQ + rbase + i) * NUM_F;
            float qs = 0.f;
#pragma unroll
            for (int f = 0; f < 16; f++) { q[i][f] = qr[f]; qs = fmaf(qr[f], qr[f], qs); }
            bound[i] = sqrtf(qs) * maxk;
            sum[i] = 0.f;
        }

        for (int c = 0; c < SEQ / ACH; c++) {
            __syncthreads();
#pragma unroll
            for (int u = 0; u < 4; u++) {
                int e4 = tid + u * 256;
                int kr = e4 >> 2, kf = (e4 & 3) * 4;
                *(float4*)&sK[kr][kf] =
                    *(const float4*)(g_kank + (size_t)(b * SEQ + c * ACH + kr) * NUM_F + kf);
            }
            __syncthreads();
#pragma unroll
            for (int kg = 0; kg < ACH / 64; kg++) {
                int jj = kg * 64 + lane * 2;
                float k0[16], k1[16];
                *(float4*)&k0[0]  = *(const float4*)&sK[jj][0];
                *(float4*)&k0[4]  = *(const float4*)&sK[jj][4];
                *(float4*)&k0[8]  = *(const float4*)&sK[jj][8];
                *(float4*)&k0[12] = *(const float4*)&sK[jj][12];
                *(float4*)&k1[0]  = *(const float4*)&sK[jj + 1][0];
                *(float4*)&k1[4]  = *(const float4*)&sK[jj + 1][4];
                *(float4*)&k1[8]  = *(const float4*)&sK[jj + 1][8];
                *(float4*)&k1[12] = *(const float4*)&sK[jj + 1][12];
                size_t jbase = (size_t)(b * SEQ) * SEQ + (size_t)c * ACH + jj;
#pragma unroll
                for (int i = 0; i < 4; i++) {
                    float s0 = 0.f, s1 = 0.f;
#pragma unroll
                    for (int f = 0; f < 16; f++) {
                        s0 = fmaf(q[i][f], k0[f], s0);
                        s1 = fmaf(q[i][f], k1[f], s1);
                    }
                    float e0 = fexp((s0 - bound[i]) * inv32);
                    float e1 = fexp((s1 - bound[i]) * inv32);
                    sum[i] += e0 + e1;
                    ((uint32_t*)g_ph)[(jbase + (size_t)(rbase + i) * SEQ) >> 1] =
                        pack2hf(e0, e1);
                }
            }
        }
#pragma unroll
        for (int i = 0; i < 4; i++) {
#pragma unroll
            for (int off = 16; off; off >>= 1)
                sum[i] += __shfl_xor_sync(0xffffffffu, sum[i], off);
            if (lane == 0) g_inv[b * SEQ + rbase + i] = 1.0f / sum[i];
        }
        __syncthreads();
    }
}

// ======================= persistent single-fp16 GEMMs =======================
// Block 128x128 tile, 8 warps each 64x32, BK=32, double-buffered LDG->reg->STS.
// B fragments loaded 2 n-tiles per ldmx4 (lanes 0-15 / 16-31).
#define MSTRIDE 40
#define TILE_B  (128 * MSTRIDE * 2)     // 10240 B
#define GM_SMEM (4 * TILE_B)            // 40960 B

// K3: v = x @ Wv^T + bv -> vT fp16.  512 tiles = 64 m x 8 n.
__global__ __launch_bounds__(256, 2) void mma_gemm_xw(const float* __restrict__ bias)
{
    extern __shared__ char smem[];
    const uint32_t sb = smem_u32(smem);
    const int tid  = threadIdx.x;
    const int lane = tid & 31, wid = tid >> 5;
    const int warp_m = wid & 1, warp_n = wid >> 1;

    const int c1 = tid + 256;
    const int ar0 = tid >> 2, ak0 = (tid & 3) * 8;
    const int ar1 = c1 >> 2,  ak1 = (c1 & 3) * 8;
    const uint32_t s0 = (uint32_t)(ar0 * MSTRIDE + ak0) * 2;
    const uint32_t s1 = (uint32_t)(ar1 * MSTRIDE + ak1) * 2;
    const int arow = warp_m * 64 + (lane & 15);
    const int acol = (lane >> 4) * 8;
    const int brow4 = warp_n * 32 + (lane & 7) + ((lane >> 4) & 1) * 8;
    const int bcol4 = ((lane >> 3) & 1) * 8;
    const int T = DIM >> 5;

    for (int tile = blockIdx.x; tile < 512; tile += gridDim.x) {
        const int m0 = (tile >> 3) * 128, n0 = (tile & 7) * 128;
        const size_t gA0 = (size_t)(m0 + ar0) * DIM + ak0;
        const size_t gA1 = (size_t)(m0 + ar1) * DIM + ak1;
        const size_t gB0 = (size_t)(n0 + ar0) * DIM + ak0;
        const size_t gB1 = (size_t)(n0 + ar1) * DIM + ak1;

        float acc[4][4][4];
#pragma unroll
        for (int mi = 0; mi < 4; mi++)
#pragma unroll
            for (int ni = 0; ni < 4; ni++)
#pragma unroll
                for (int rr = 0; rr < 4; rr++) acc[mi][ni][rr] = 0.f;

        uint4 rg[4];
#define LOADG(K0) do {                                                 \
            rg[0] = *(const uint4*)(g_xf + gA0 + (K0));                \
            rg[1] = *(const uint4*)(g_xf + gA1 + (K0));                \
            rg[2] = *(const uint4*)(g_wf + gB0 + (K0));                \
            rg[3] = *(const uint4*)(g_wf + gB1 + (K0));                \
        } while (0)
#define STORES(S) do {                                                 \
            char* base = smem + (S) * 2 * TILE_B;                      \
            *(uint4*)(base + s0)          = rg[0];                     \
            *(uint4*)(base + s1)          = rg[1];                     \
            *(uint4*)(base + TILE_B + s0) = rg[2];                     \
            *(uint4*)(base + TILE_B + s1) = rg[3];                     \
        } while (0)

        LOADG(0);
        __syncthreads();          // smem free of previous tile's readers
        STORES(0);
        __syncthreads();

        for (int t = 0; t < T; t++) {
            if (t + 1 < T) LOADG((t + 1) << 5);
            uint32_t base = sb + (uint32_t)(t & 1) * 2 * TILE_B;
#pragma unroll
            for (int kk = 0; kk < 32; kk += 16) {
                uint32_t ah[4][4], bh[4][2];
#pragma unroll
                for (int mi = 0; mi < 4; mi++) {
                    uint32_t ad = (uint32_t)(((arow + mi * 16) * MSTRIDE + kk + acol) * 2);
                    ldmx4(ah[mi], base + ad);
                }
#pragma unroll
                for (int p = 0; p < 2; p++) {
                    uint32_t bd = (uint32_t)(((brow4 + p * 16) * MSTRIDE + kk + bcol4) * 2);
                    ldmx4(&bh[p * 2][0], base + TILE_B + bd);
                }
#pragma unroll
                for (int mi = 0; mi < 4; mi++)
#pragma unroll
                    for (int ni = 0; ni < 4; ni++)
                        mma_f16(acc[mi][ni], ah[mi], bh[ni]);
            }
            if (t + 1 < T) {
                STORES((t + 1) & 1);
                __syncthreads();
            }
        }
#undef LOADG
#undef STORES

        // epilogue: two 64-column halves, buffer [64][132] f32 in smem
        float* st = (float*)smem;
        int bz  = m0 >> 11;
        int m0s = m0 & (SEQ - 1);
#pragma unroll
        for (int half = 0; half < 2; half++) {
            __syncthreads();
            if ((warp_n >> 1) == half) {
                int wn = warp_n & 1;
#pragma unroll
                for (int mi = 0; mi < 4; mi++) {
                    int rowl = warp_m * 64 + mi * 16 + (lane >> 2);
#pragma unroll
                    for (int ni = 0; ni < 4; ni++) {
                        int coll = wn * 32 + ni * 8 + (lane & 3) * 2;
                        int gcol = half * 64 + coll;
                        float b0 = bias[n0 + gcol], b1 = bias[n0 + gcol + 1];
                        st[coll * 132 + rowl]           = acc[mi][ni][0] + b0;
                        st[(coll + 1) * 132 + rowl]     = acc[mi][ni][1] + b1;
                        st[coll * 132 + rowl + 8]       = acc[mi][ni][2] + b0;
                        st[(coll + 1) * 132 + rowl + 8] = acc[mi][ni][3] + b1;
                    }
                }
            }
            __syncthreads();
            for (int w = tid; w < 64 * 64; w += 256) {
                int d = w >> 6, mp = w & 63;
                float v0 = st[d * 132 + mp * 2];
                float v1 = st[d * 132 + mp * 2 + 1];
                size_t idx = (((size_t)(bz * DIM + n0 + half * 64 + d) * SEQ + m0s) >> 1) + mp;
                ((uint32_t*)g_vt)[idx] = pack2hf(v0, v1);
            }
        }
    }
}

// K5: out = (P @ v) * inv_sum.  512 tiles = 4 z x 16 m x 8 n.
__global__ __launch_bounds__(256, 2) void mma_gemm_pv(float* __restrict__ Cout)
{
    extern __shared__ char smem[];
    const uint32_t sb = smem_u32(smem);
    const int tid  = threadIdx.x;
    const int lane = tid & 31, wid = tid >> 5;
    const int warp_m = wid & 1, warp_n = wid >> 1;

    const int c1 = tid + 256;
    const int ar0 = tid >> 2, ak0 = (tid & 3) * 8;
    const int ar1 = c1 >> 2,  ak1 = (c1 & 3) * 8;
    const uint32_t s0 = (uint32_t)(ar0 * MSTRIDE + ak0) * 2;
    const uint32_t s1 = (uint32_t)(ar1 * MSTRIDE + ak1) * 2;
    const int arow = warp_m * 64 + (lane & 15);
    const int acol = (lane >> 4) * 8;
    const int brow4 = warp_n * 32 + (lane & 7) + ((lane >> 4) & 1) * 8;
    const int bcol4 = ((lane >> 3) & 1) * 8;
    const int T = SEQ >> 5;

    for (int tile = blockIdx.x; tile < 512; tile += gridDim.x) {
        const int z  = tile & 3;
        const int tt = tile >> 2;
        const int m0 = (tt >> 3) * 128, n0 = (tt & 7) * 128;
        const __half* pP = g_ph + (size_t)z * SEQ * SEQ;
        const __half* pV = g_vt + (size_t)z * DIM * SEQ;
        const size_t gA0 = (size_t)(m0 + ar0) * SEQ + ak0;
        const size_t gA1 = (size_t)(m0 + ar1) * SEQ + ak1;
        const size_t gB0 = (size_t)(n0 + ar0) * SEQ + ak0;
        const size_t gB1 = (size_t)(n0 + ar1) * SEQ + ak1;

        float acc[4][4][4];
#pragma unroll
        for (int mi = 0; mi < 4; mi++)
#pragma unroll
            for (int ni = 0; ni < 4; ni++)
#pragma unroll
                for (int rr = 0; rr < 4; rr++) acc[mi][ni][rr] = 0.f;

        uint4 rg[4];
#define PLOADG(K0) do {                                                \
            rg[0] = *(const uint4*)(pP + gA0 + (K0));                  \
            rg[1] = *(const uint4*)(pP + gA1 + (K0));                  \
            rg[2] = *(const uint4*)(pV + gB0 + (K0));                  \
            rg[3] = *(const uint4*)(pV + gB1 + (K0));                  \
        } while (0)
#define PSTORES(S) do {                                                \
            char* base = smem + (S) * 2 * TILE_B;                      \
            *(uint4*)(base + s0)          = rg[0];                     \
            *(uint4*)(base + s1)          = rg[1];                     \
            *(uint4*)(base + TILE_B + s0) = rg[2];                     \
            *(uint4*)(base + TILE_B + s1) = rg[3];                     \
        } while (0)

        PLOADG(0);
        __syncthreads();          // smem free of previous tile's readers
        PSTORES(0);
        __syncthreads();

        for (int t = 0; t < T; t++) {
            if (t + 1 < T) PLOADG((t + 1) << 5);
            uint32_t base = sb + (uint32_t)(t & 1) * 2 * TILE_B;
#pragma unroll
            for (int kk = 0; kk < 32; kk += 16) {
                uint32_t ah[4][4], bh[4][2];
#pragma unroll
                for (int mi = 0; mi < 4; mi++) {
                    uint32_t ad = (uint32_t)(((arow + mi * 16) * MSTRIDE + kk + acol) * 2);
                    ldmx4(ah[mi], base + ad);
                }
#pragma unroll
                for (int p = 0; p < 2; p++) {
                    uint32_t bd = (uint32_t)(((brow4 + p * 16) * MSTRIDE + kk + bcol4) * 2);
                    ldmx4(&bh[p * 2][0], base + TILE_B + bd);
                }
#pragma unroll
                for (int mi = 0; mi < 4; mi++)
#pragma unroll
                    for (int ni = 0; ni < 4; ni++)
                        mma_f16(acc[mi][ni], ah[mi], bh[ni]);
            }
            if (t + 1 < T) {
                PSTORES((t + 1) & 1);
                __syncthreads();
            }
        }
#undef PLOADG
#undef PSTORES

        float* C = Cout + (size_t)z * SEQ * DIM;
#pragma unroll
        for (int mi = 0; mi < 4; mi++) {
            int rowl = warp_m * 64 + mi * 16 + (lane >> 2);
            float inv0 = g_inv[z * SEQ + m0 + rowl];
            float inv1 = g_inv[z * SEQ + m0 + rowl + 8];
#pragma unroll
            for (int ni = 0; ni < 4; ni++) {
                int col = n0 + warp_n * 32 + ni * 8 + (lane & 3) * 2;
                *(float2*)&C[(size_t)(m0 + rowl) * DIM + col] =
                    make_float2(acc[mi][ni][0] * inv0, acc[mi][ni][1] * inv0);
                *(float2*)&C[(size_t)(m0 + rowl + 8) * DIM + col] =
                    make_float2(acc[mi][ni][2] * inv1, acc[mi][ni][3] * inv1);
            }
        }
    }
}

// ======================= launch =============================================
extern "C" void kernel_launch(void* const* d_in, const int* in_sizes, int n_in,
                              void* d_out, int out_size)
{
    const float* x     = (const float*)d_in[0];
    const float* basis = (const float*)d_in[1];
    const float* Wq    = (const float*)d_in[2];
    const float* bq    = (const float*)d_in[3];
    const float* Wk    = (const float*)d_in[4];
    const float* bk    = (const float*)d_in[5];
    const float* Wv    = (const float*)d_in[6];
    const float* bv    = (const float*)d_in[7];
    float* out = (float*)d_out;

    int sms = 148;
    cudaDeviceGetAttribute(&sms, cudaDevAttrMultiProcessorCount, 0);
    int gemm_grid = 2 * sms;

    cudaFuncSetAttribute(mma_gemm_xw, cudaFuncAttributeMaxDynamicSharedMemorySize, GM_SMEM);
    cudaFuncSetAttribute(mma_gemm_pv, cudaFuncAttributeMaxDynamicSharedMemorySize, GM_SMEM);

    // fp16 conversions (x and Wv, one launch)
    tohalf2_kernel<<<(NX4 + NW4) / 256, 256>>>(x, Wv);

    // fold (fp16 C + biases + maxk reset)
    fold_kernel<<<dim3(4, 32), 256>>>(basis, Wq, bq, Wk, bk);

    // kan via mma.sync + per-batch key max
    kan_mma_kernel<<<MTOK / 64, 128>>>();
    knorm_kernel<<<MTOK / 256, 256>>>();

    // K3: v = x @ Wv^T + bv -> vT fp16 (persistent)
    mma_gemm_xw<<<gemm_grid, 256, GM_SMEM>>>(bv);

    // K4: fused scores + softmax (unnormalized exp fp16 + 1/sum)
    attn_kernel<<<MTOK / 64, 256>>>();

    // K5: out = (P @ v) * inv_sum  (persistent)
    mma_gemm_pv<<<gemm_grid, 256, GM_SMEM>>>(out);
}